// round 12
// baseline (speedup 1.0000x reference)
#include <cuda_runtime.h>
#include <cuda_fp16.h>
#include <math.h>
#include <stdint.h>

#define T    2048
#define HDIM 1024
#define FDIM 3584
#define NEXP 8
#define NH   16
#define SEQ  2048
#define NSEL 204   // int(0.1 * 2048)

#define NWELEM (NEXP * FDIM * HDIM)   // 29360128 per weight tensor

// ---------------- device scratch (no allocations allowed) ----------------
__device__ float g_scores[T];
__device__ float g_l1[T];
__device__ int   g_sel[T * 2];
__device__ float g_rw[T * 2];
__device__ int   g_top1prune[T];
__device__ int   g_low[T];
__device__ int   g_high[T];
__device__ int   g_cnt[NEXP];
__device__ int   g_ptok[NEXP * T];
__device__ float g_pw[NEXP * T];
__device__ __half g_xh[T * HDIM];
__device__ __half g_w1h[NWELEM];
__device__ __half g_w3h[NWELEM];
__device__ __half g_w2h[NWELEM];
__device__ __half g_acth[(size_t)NEXP * T * FDIM];  // fp16 activations

// ============================ helpers =====================================
__device__ __forceinline__ uint32_t smem_u32(const void* p) {
    uint32_t a;
    asm("{ .reg .u64 t; cvta.to.shared.u64 t, %1; cvt.u32.u64 %0, t; }" : "=r"(a) : "l"(p));
    return a;
}
__device__ __forceinline__ void ldm_x4(uint32_t r[4], uint32_t addr) {
    asm volatile("ldmatrix.sync.aligned.m8n8.x4.shared.b16 {%0,%1,%2,%3}, [%4];"
                 : "=r"(r[0]), "=r"(r[1]), "=r"(r[2]), "=r"(r[3]) : "r"(addr));
}
__device__ __forceinline__ void mma4(float d[4], const uint32_t a[4], const uint32_t b[2]) {
    asm volatile("mma.sync.aligned.m16n8k16.row.col.f32.f16.f16.f32 "
                 "{%0,%1,%2,%3}, {%4,%5,%6,%7}, {%8,%9}, {%0,%1,%2,%3};"
                 : "+f"(d[0]), "+f"(d[1]), "+f"(d[2]), "+f"(d[3])
                 : "r"(a[0]), "r"(a[1]), "r"(a[2]), "r"(a[3]), "r"(b[0]), "r"(b[1]));
}
__device__ __forceinline__ void cpa16(uint32_t s, const void* g) {
    asm volatile("cp.async.ca.shared.global [%0], [%1], 16;" :: "r"(s), "l"(g) : "memory");
}
#define CP_COMMIT() asm volatile("cp.async.commit_group;" ::: "memory")
#define CP_WAIT0()  asm volatile("cp.async.wait_group 0;" ::: "memory")

__device__ __forceinline__ uint32_t pkh(float a, float b) {
    return (uint32_t)__half_as_ushort(__float2half(a))
         | ((uint32_t)__half_as_ushort(__float2half(b)) << 16);
}

// row stride: 64 fp16 (128B) + 16B pad = 144B (conflict-free ldmatrix)
#define RS2 144
// gemm1 per-stage: A 128x144 @0, B1 64x144 @18432, B3 64x144 @27648
#define G1_STG   36864
#define G1_SMEM  (2 * G1_STG + 1024)
// gemm2 per-stage: A 128x144 @0, B 128x144 @18432
#define G2_STG   36864
#define G2_SMEM  (2 * G2_STG + 512)

// ---------------- convert: fp32 -> fp16, 4 float4/thread ------------------
__global__ void cvt_kernel(const float4* __restrict__ src, uint2* __restrict__ dst, int n4) {
    int base = (blockIdx.x * blockDim.x) * 4 + threadIdx.x;
    #pragma unroll
    for (int it = 0; it < 4; it++) {
        int i = base + it * 256;
        if (i < n4) {
            float4 v = src[i];
            uint2 u;
            u.x = pkh(v.x, v.y);
            u.y = pkh(v.z, v.w);
            dst[i] = u;
        }
    }
}

// ---------------- kernel 1: router ---------------------------------------
__global__ void router_kernel(const float* __restrict__ x,
                              const float* __restrict__ gw,
                              float* logits_out) {
    int t = blockIdx.x;
    int lane = threadIdx.x & 31;
    int w = threadIdx.x >> 5;
    __shared__ float s_logit[NEXP];
    __shared__ float s_l1;

    const float* xr = x + (size_t)t * HDIM;
    const float* ge = gw + (size_t)w * HDIM;
    float acc = 0.f, l1 = 0.f;
    for (int i = lane; i < HDIM; i += 32) {
        float xv = xr[i];
        acc += xv * ge[i];
        l1 += fabsf(xv);
    }
    #pragma unroll
    for (int o = 16; o; o >>= 1) {
        acc += __shfl_xor_sync(0xffffffffu, acc, o);
        l1  += __shfl_xor_sync(0xffffffffu, l1, o);
    }
    if (lane == 0) {
        s_logit[w] = acc;
        if (w == 0) s_l1 = l1;
    }
    __syncthreads();
    if (threadIdx.x == 0) {
        float p[NEXP];
        float mx = s_logit[0];
        for (int e = 1; e < NEXP; e++) if (s_logit[e] > mx) mx = s_logit[e];
        float sum = 0.f;
        for (int e = 0; e < NEXP; e++) { p[e] = expf(s_logit[e] - mx); sum += p[e]; }
        float inv = 1.f / sum;
        for (int e = 0; e < NEXP; e++) p[e] *= inv;
        int i0 = 0;
        for (int e = 1; e < NEXP; e++) if (p[e] > p[i0]) i0 = e;
        int i1 = (i0 == 0) ? 1 : 0;
        for (int e = 0; e < NEXP; e++) if (e != i0 && p[e] > p[i1]) i1 = e;
        g_sel[2 * t] = i0;  g_sel[2 * t + 1] = i1;
        g_rw[2 * t] = p[i0]; g_rw[2 * t + 1] = p[i1];
        g_top1prune[t] = (p[i1] < 0.5f * p[i0]) ? 1 : 0;
        g_l1[t] = s_l1;
        if (logits_out) {
            for (int e = 0; e < NEXP; e++) logits_out[(size_t)t * NEXP + e] = s_logit[e];
        }
    }
}

// ---------------- kernel 2: attention-score reduction --------------------
__global__ void attn_kernel(const float* __restrict__ attn) {
    int i = blockIdx.x;
    float s = 0.f;
    for (int h = 0; h < NH; h++) {
        const float4* row = reinterpret_cast<const float4*>(attn + ((size_t)h * SEQ + i) * SEQ);
        for (int j = threadIdx.x; j < SEQ / 4; j += 256) {
            float4 v = row[j];
            s += v.x + v.y + v.z + v.w;
        }
    }
    __shared__ float red[256];
    red[threadIdx.x] = s;
    __syncthreads();
    for (int st = 128; st > 0; st >>= 1) {
        if (threadIdx.x < st) red[threadIdx.x] += red[threadIdx.x + st];
        __syncthreads();
    }
    if (threadIdx.x == 0)
        g_scores[i] = red[0] / (16.f * (float)(SEQ - i)) * g_l1[i];
}

// ---------------- kernel 3: single bitonic sort + routing finalize -------
__global__ void route_finalize_kernel() {
    __shared__ float sval[T];
    __shared__ int   sidx[T];
    int tid = threadIdx.x;  // 1024 threads

    for (int t = tid; t < T; t += 1024) {
        g_low[t] = 0; g_high[t] = 0;
        sval[t] = g_scores[t]; sidx[t] = t;
    }
    if (tid < NEXP) g_cnt[tid] = 0;
    __syncthreads();

    for (int k = 2; k <= T; k <<= 1) {
        for (int j = k >> 1; j > 0; j >>= 1) {
            #pragma unroll
            for (int s = 0; s < 2; s++) {
                int i = tid + s * 1024;
                int ixj = i ^ j;
                if (ixj > i) {
                    float va = sval[i], vb = sval[ixj];
                    int ia = sidx[i], ib = sidx[ixj];
                    bool aBeforeB = (va < vb) || (va == vb && ia < ib);
                    bool up = ((i & k) == 0);
                    bool doswap = up ? !aBeforeB : aBeforeB;
                    if (doswap) {
                        sval[i] = vb; sval[ixj] = va;
                        sidx[i] = ib; sidx[ixj] = ia;
                    }
                }
            }
            __syncthreads();
        }
    }
    for (int r = tid; r < NSEL; r += 1024) {
        g_low[sidx[r]] = 1;
        g_high[sidx[T - 1 - r]] = 1;
    }
    __syncthreads();

    for (int t = tid; t < T; t += 1024) {
        float r0 = g_rw[2 * t], r1 = g_rw[2 * t + 1];
        float n0 = 1.f;
        float n1 = g_top1prune[t] ? 0.f : 1.f;
        if (g_low[t])  { n0 = 0.f; n1 = 0.f; }
        if (g_high[t]) { n0 = 1.f; n1 = 1.f; }
        r0 *= n0; r1 *= n1;
        float d = r0 + r1;
        if (d > 0.f) { r0 /= d; r1 /= d; }
        if (r0 > 0.f) {
            int e = g_sel[2 * t];
            int p = atomicAdd(&g_cnt[e], 1);
            g_ptok[e * T + p] = t;  g_pw[e * T + p] = r0;
        }
        if (r1 > 0.f) {
            int e = g_sel[2 * t + 1];
            int p = atomicAdd(&g_cnt[e], 1);
            g_ptok[e * T + p] = t;  g_pw[e * T + p] = r1;
        }
    }
}

// ---------------- gemm1: fp16 cp.async, 128x64 tile, warps 4x2 -----------
__global__ void __launch_bounds__(256, 2) gemm1_mma() {
    extern __shared__ char sm[];
    const int e = blockIdx.z;
    const int Ne = g_cnt[e];
    const int m0 = blockIdx.x * 128;
    if (m0 >= Ne) return;
    const int f0 = blockIdx.y * 64;
    const int tid = threadIdx.x;
    const int lane = tid & 31, wid = tid >> 5;
    const int wm = wid & 3, wn = wid >> 2;   // 4m x 2n warp grid

    const uint32_t sb = smem_u32(sm);
    int*   stok = reinterpret_cast<int*>(sm + 2 * G1_STG);
    float* spw  = reinterpret_cast<float*>(sm + 2 * G1_STG + 512);
    if (tid < 128) {
        int m = m0 + tid; int tk = 0; float pw = 0.f;
        if (m < Ne) { tk = g_ptok[e * T + m]; pw = g_pw[e * T + m]; }
        stok[tid] = tk; spw[tid] = pw;
    }
    __syncthreads();

    // producer mapping: per stage A 4 chunks/thread, B 4 chunks/thread (16B)
    int abase[4]; uint32_t aoff[4];
    int bbase[4]; uint32_t boff[4];
    const __half* wsrc[4];
    #pragma unroll
    for (int i = 0; i < 4; i++) {
        int idx = tid + i * 256;               // [0,1024): A chunks
        int ar = idx >> 3, c8 = (idx & 7) << 3;
        abase[i] = stok[ar] * HDIM + c8;
        aoff[i]  = (uint32_t)(ar * RS2 + c8 * 2);
        int bm = idx >> 9, br = (idx >> 3) & 63;  // B chunks
        wsrc[i]  = bm ? g_w3h : g_w1h;
        bbase[i] = (e * FDIM + f0 + br) * HDIM + c8;
        boff[i]  = (uint32_t)(18432 + bm * 9216 + br * RS2 + c8 * 2);
    }

    auto issue_stage = [&](int s) {
        uint32_t bp = sb + (uint32_t)(s & 1) * G1_STG;
        int k0 = s * 64;
        #pragma unroll
        for (int i = 0; i < 4; i++) cpa16(bp + aoff[i], g_xh + abase[i] + k0);
        #pragma unroll
        for (int i = 0; i < 4; i++) cpa16(bp + boff[i], wsrc[i] + bbase[i] + k0);
        CP_COMMIT();
    };

    issue_stage(0);
    CP_WAIT0();
    __syncthreads();

    const int lrow = lane & 15;
    const int lhik = ((lane >> 4) & 1) * 16;
    const int bn = (lane & 7) + ((lane >> 4) & 1) * 8;
    const int bhk = ((lane >> 3) & 1) * 16;

    float hc[2][4][4] = {{{0.f}}}, gc[2][4][4] = {{{0.f}}};

    auto mma_blk = [&](uint32_t bb, int kk) {
        const uint32_t koff = (uint32_t)kk * 32;
        uint32_t Ah[2][4];
        #pragma unroll
        for (int fm = 0; fm < 2; fm++)
            ldm_x4(Ah[fm], bb + (uint32_t)((wm * 32 + fm * 16 + lrow) * RS2) + koff + lhik);
        #pragma unroll
        for (int fnh = 0; fnh < 2; fnh++) {
            uint32_t bo = (uint32_t)((wn * 32 + fnh * 16 + bn) * RS2) + koff + bhk;
            uint32_t B1[4], B3[4];
            ldm_x4(B1, bb + 18432 + bo);
            ldm_x4(B3, bb + 27648 + bo);
            #pragma unroll
            for (int fm = 0; fm < 2; fm++)
                #pragma unroll
                for (int f2 = 0; f2 < 2; f2++) {
                    int fn = fnh * 2 + f2;
                    mma4(hc[fm][fn], Ah[fm], B1 + 2 * f2);
                    mma4(gc[fm][fn], Ah[fm], B3 + 2 * f2);
                }
        }
    };

    for (int s = 0; s < 16; s++) {
        const uint32_t bb = sb + (uint32_t)(s & 1) * G1_STG;
        const bool more = (s + 1 < 16);
        if (more) issue_stage(s + 1);
        mma_blk(bb, 0);
        mma_blk(bb, 1);
        mma_blk(bb, 2);
        mma_blk(bb, 3);
        if (more) { CP_WAIT0(); __syncthreads(); }
    }

    // epilogue: act = pw * g * silu(h), write fp16
    const int g = lane >> 2, tq = lane & 3;
    #pragma unroll
    for (int fm = 0; fm < 2; fm++) {
        #pragma unroll
        for (int fn = 0; fn < 4; fn++) {
            int rl = wm * 32 + fm * 16 + g;
            int c  = f0 + wn * 32 + fn * 8 + 2 * tq;
            float pw0 = spw[rl], pw1 = spw[rl + 8];
            float h0 = hc[fm][fn][0], h1 = hc[fm][fn][1];
            float h2 = hc[fm][fn][2], h3 = hc[fm][fn][3];
            float a0 = pw0 * gc[fm][fn][0] * (h0 / (1.f + expf(-h0)));
            float a1 = pw0 * gc[fm][fn][1] * (h1 / (1.f + expf(-h1)));
            float a2 = pw1 * gc[fm][fn][2] * (h2 / (1.f + expf(-h2)));
            float a3 = pw1 * gc[fm][fn][3] * (h3 / (1.f + expf(-h3)));
            *reinterpret_cast<uint32_t*>(g_acth + ((size_t)(e * T + m0 + rl)) * FDIM + c) = pkh(a0, a1);
            *reinterpret_cast<uint32_t*>(g_acth + ((size_t)(e * T + m0 + rl + 8)) * FDIM + c) = pkh(a2, a3);
        }
    }
}

// ---------------- gemm2: fp16 cp.async, 128x128 tile, warps 2x4 ----------
__global__ void __launch_bounds__(256, 2) gemm2_mma(float* __restrict__ out) {
    extern __shared__ char sm[];
    const int e = blockIdx.z;
    const int Ne = g_cnt[e];
    const int m0 = blockIdx.x * 128;
    if (m0 >= Ne) return;
    const int n0 = blockIdx.y * 128;
    const int tid = threadIdx.x;
    const int lane = tid & 31, wid = tid >> 5;
    const int wm = wid & 1, wn = wid >> 1;   // 2m x 4n warp grid

    const uint32_t sb = smem_u32(sm);
    int* stok = reinterpret_cast<int*>(sm + 2 * G2_STG);
    if (tid < 128) {
        int m = m0 + tid; int tk = 0;
        if (m < Ne) tk = g_ptok[e * T + m];
        stok[tid] = tk;
    }
    __syncthreads();

    int abase[4]; uint32_t aoff[4];
    int bbase[4]; uint32_t boff[4];
    #pragma unroll
    for (int i = 0; i < 4; i++) {
        int idx = tid + i * 256;
        int r = idx >> 3, c8 = (idx & 7) << 3;
        abase[i] = (e * T + m0 + r) * FDIM + c8;
        aoff[i]  = (uint32_t)(r * RS2 + c8 * 2);
        bbase[i] = (e * HDIM + n0 + r) * FDIM + c8;
        boff[i]  = (uint32_t)(18432 + r * RS2 + c8 * 2);
    }

    auto issue_stage = [&](int s) {
        uint32_t bp = sb + (uint32_t)(s & 1) * G2_STG;
        int k0 = s * 64;
        #pragma unroll
        for (int i = 0; i < 4; i++) cpa16(bp + aoff[i], g_acth + abase[i] + k0);
        #pragma unroll
        for (int i = 0; i < 4; i++) cpa16(bp + boff[i], g_w2h + bbase[i] + k0);
        CP_COMMIT();
    };

    issue_stage(0);
    CP_WAIT0();
    __syncthreads();

    const int lrow = lane & 15;
    const int lhik = ((lane >> 4) & 1) * 16;
    const int bn = (lane & 7) + ((lane >> 4) & 1) * 8;
    const int bhk = ((lane >> 3) & 1) * 16;

    float acc[4][4][4] = {{{0.f}}};

    auto mma_blk = [&](uint32_t bb, int kk) {
        const uint32_t koff = (uint32_t)kk * 32;
        uint32_t Bf[2][4];
        #pragma unroll
        for (int f2 = 0; f2 < 2; f2++)
            ldm_x4(Bf[f2], bb + 18432 + (uint32_t)((wn * 32 + f2 * 16 + bn) * RS2) + koff + bhk);
        #pragma unroll
        for (int fm = 0; fm < 4; fm++) {
            uint32_t Af[4];
            ldm_x4(Af, bb + (uint32_t)((wm * 64 + fm * 16 + lrow) * RS2) + koff + lhik);
            #pragma unroll
            for (int f2 = 0; f2 < 2; f2++)
                #pragma unroll
                for (int j = 0; j < 2; j++)
                    mma4(acc[fm][f2 * 2 + j], Af, Bf[f2] + 2 * j);
        }
    };

    const int NST = FDIM / 64;  // 56
    for (int s = 0; s < NST; s++) {
        const uint32_t bb = sb + (uint32_t)(s & 1) * G2_STG;
        const bool more = (s + 1 < NST);
        if (more) issue_stage(s + 1);
        mma_blk(bb, 0);
        mma_blk(bb, 1);
        mma_blk(bb, 2);
        mma_blk(bb, 3);
        if (more) { CP_WAIT0(); __syncthreads(); }
    }

    // epilogue: scatter-add fp32
    const int g = lane >> 2, tq = lane & 3;
    #pragma unroll
    for (int fm = 0; fm < 4; fm++) {
        #pragma unroll
        for (int fn = 0; fn < 4; fn++) {
            int rl = wm * 64 + fm * 16 + g;
            int c  = n0 + wn * 32 + fn * 8 + 2 * tq;
            if (m0 + rl < Ne) {
                float* o = out + (size_t)stok[rl] * HDIM + c;
                atomicAdd(o + 0, acc[fm][fn][0]);
                atomicAdd(o + 1, acc[fm][fn][1]);
            }
            if (m0 + rl + 8 < Ne) {
                float* o = out + (size_t)stok[rl + 8] * HDIM + c;
                atomicAdd(o + 0, acc[fm][fn][2]);
                atomicAdd(o + 1, acc[fm][fn][3]);
            }
        }
    }
}

// ---------------- launch ---------------------------------------------------
extern "C" void kernel_launch(void* const* d_in, const int* in_sizes, int n_in,
                              void* d_out, int out_size) {
    const float* x    = (const float*)d_in[0];
    const float* attn = (const float*)d_in[1];
    const float* gw   = (const float*)d_in[2];
    const float* w1   = (const float*)d_in[3];
    const float* w2   = (const float*)d_in[4];
    const float* w3   = (const float*)d_in[5];

    float* out = (float*)d_out;
    float* logits = (out_size >= (int)(T * HDIM + T * NEXP)) ? out + (size_t)T * HDIM
                                                             : nullptr;

    cudaFuncSetAttribute(gemm1_mma, cudaFuncAttributeMaxDynamicSharedMemorySize, G1_SMEM);
    cudaFuncSetAttribute(gemm2_mma, cudaFuncAttributeMaxDynamicSharedMemorySize, G2_SMEM);

    __half* d_xh;  cudaGetSymbolAddress((void**)&d_xh,  g_xh);
    __half* d_w1h; cudaGetSymbolAddress((void**)&d_w1h, g_w1h);
    __half* d_w3h; cudaGetSymbolAddress((void**)&d_w3h, g_w3h);
    __half* d_w2h; cudaGetSymbolAddress((void**)&d_w2h, g_w2h);

    const int NW4 = NWELEM / 4;        // 7340032
    const int NX4 = T * HDIM / 4;      // 524288
    const int CVB = 256 * 4;           // elements-of-float4 per block

    // fork a side stream (capture-safe event fork/join pattern)
    cudaStream_t s2;
    cudaStreamCreateWithFlags(&s2, cudaStreamNonBlocking);
    cudaEvent_t evFork, evRoute, evW2;
    cudaEventCreateWithFlags(&evFork,  cudaEventDisableTiming);
    cudaEventCreateWithFlags(&evRoute, cudaEventDisableTiming);
    cudaEventCreateWithFlags(&evW2,    cudaEventDisableTiming);

    cudaEventRecord(evFork, 0);
    cudaStreamWaitEvent(s2, evFork, 0);

    // stream 0: conversions needed by gemm1
    cudaMemsetAsync(d_out, 0, (size_t)T * HDIM * sizeof(float));
    cvt_kernel<<<(NX4 + CVB - 1) / CVB, 256>>>((const float4*)x,  (uint2*)d_xh,  NX4);
    cvt_kernel<<<(NW4 + CVB - 1) / CVB, 256>>>((const float4*)w1, (uint2*)d_w1h, NW4);
    cvt_kernel<<<(NW4 + CVB - 1) / CVB, 256>>>((const float4*)w3, (uint2*)d_w3h, NW4);

    // stream s2: routing pipeline, then w2 conversion (overlaps gemm1)
    router_kernel<<<T, 256, 0, s2>>>(x, gw, logits);
    attn_kernel<<<SEQ, 256, 0, s2>>>(attn);
    route_finalize_kernel<<<1, 1024, 0, s2>>>();
    cudaEventRecord(evRoute, s2);
    cvt_kernel<<<(NW4 + CVB - 1) / CVB, 256, 0, s2>>>((const float4*)w2, (uint2*)d_w2h, NW4);
    cudaEventRecord(evW2, s2);

    // join: gemm1 needs routing + x/w1/w3 fp16
    cudaStreamWaitEvent(0, evRoute, 0);
    gemm1_mma<<<dim3(16, FDIM / 64, NEXP), 256, G1_SMEM>>>();

    // join: gemm2 needs w2 fp16 + act
    cudaStreamWaitEvent(0, evW2, 0);
    gemm2_mma<<<dim3(16, HDIM / 128, NEXP), 256, G2_SMEM>>>(out);
}